// round 9
// baseline (speedup 1.0000x reference)
#include <cuda_runtime.h>
#include <cuda_fp16.h>
#include <cstdint>

#define S_SZ 2048
#define D_SZ 1024
#define H_SZ 16
#define HD_SZ 64
#define B_SZ 2
#define BH_SZ (B_SZ * H_SZ)       // 32
#define TOK_SZ (B_SZ * S_SZ)      // 4096
#define KLOG 0.18033688011112042f // 0.125 * log2(e)
#define KSTR 80                   // halves per row in fp16 smem tiles

// Scratch (device globals: allocation-free rule)
__device__ __half g_Xh[TOK_SZ * D_SZ];        // fp16 X, k16-permuted D
__device__ __half g_Wh[3 * D_SZ * D_SZ];      // fp16 W^T (n-major), k16-permuted k; Wq*KLOG
__device__ __half g_Qh[BH_SZ * S_SZ * HD_SZ]; // fp16 Q (KLOG-scaled), k16-permuted d
__device__ __half g_Kh[BH_SZ * S_SZ * HD_SZ]; // fp16 K, k16-permuted d
__device__ float  g_V[BH_SZ * S_SZ * HD_SZ];  // full fp32
__device__ float  g_Ri[BH_SZ * S_SZ];         // 1 / rowsum(exp2(scores2))
__device__ float  g_w[BH_SZ * S_SZ];          // mean attention weight per key

// ---------------------------------------------------------------------------
__device__ __forceinline__ void mma16h(float c[4], const unsigned a[4], const unsigned b[2]) {
    asm volatile(
        "mma.sync.aligned.m16n8k16.row.col.f32.f16.f16.f32 "
        "{%0,%1,%2,%3}, {%4,%5,%6,%7}, {%8,%9}, {%0,%1,%2,%3};\n"
        : "+f"(c[0]), "+f"(c[1]), "+f"(c[2]), "+f"(c[3])
        : "r"(a[0]), "r"(a[1]), "r"(a[2]), "r"(a[3]), "r"(b[0]), "r"(b[1]));
}

// 2^x on the MUFU pipe (input already in log2 domain).
__device__ __forceinline__ float ex2(float x) {
    float y; asm("ex2.approx.f32 %0, %1;" : "=f"(y) : "f"(x)); return y;
}

__device__ __forceinline__ void cpa16(uint32_t dst, const void* src) {
    asm volatile("cp.async.ca.shared.global [%0], [%1], 16;\n" :: "r"(dst), "l"(src));
}
__device__ __forceinline__ void cp_commit() { asm volatile("cp.async.commit_group;\n"); }
template <int N> __device__ __forceinline__ void cp_wait() {
    asm volatile("cp.async.wait_group %0;\n" :: "n"(N));
}

// slot within a 16-group for EVEN logical index r (odd index = slot+1)
__device__ __forceinline__ int slot_e(int r) {
    return 4 * ((r & 7) >> 1) + ((r >> 3) << 1);
}

// ---------------------------------------------------------------------------
// Prep X: fp16 convert with k16 permutation on the D (reduction) dim.
// ---------------------------------------------------------------------------
__global__ __launch_bounds__(256) void prep_x(const float* __restrict__ X) {
    const int N4 = TOK_SZ * D_SZ / 4;
    int stride = gridDim.x * blockDim.x;
    for (int i = blockIdx.x * blockDim.x + threadIdx.x; i < N4; i += stride) {
        int m = i >> 8, c4 = (i & 255) << 2;          // 4 consecutive k, c4 % 4 == 0
        float4 v = *(const float4*)(X + (size_t)m * D_SZ + c4);
        int base = (size_t)0 + (c4 & ~15), r = c4 & 15;
        int s0 = base + slot_e(r), s2 = base + slot_e(r + 2);
        __half* row = g_Xh + (size_t)m * D_SZ;
        *(__half2*)(row + s0) = __floats2half2_rn(v.x, v.y);
        *(__half2*)(row + s2) = __floats2half2_rn(v.z, v.w);
    }
}

// ---------------------------------------------------------------------------
// Prep W: transpose to [n][k], fp16, k16 permutation on k; fold KLOG into Wq.
// Grid (k-tiles, n-tiles, 3), 32x32 tiles, 256 threads.
// ---------------------------------------------------------------------------
__global__ __launch_bounds__(256) void prep_w(const float* __restrict__ Wq,
                                              const float* __restrict__ Wk,
                                              const float* __restrict__ Wv) {
    __shared__ float s[32][33];
    const int sel = blockIdx.z;
    const int k0 = blockIdx.x * 32, n0 = blockIdx.y * 32;
    const float* Wp = (sel == 0) ? Wq : (sel == 1) ? Wk : Wv;
    const float scale = (sel == 0) ? KLOG : 1.0f;
    const int tx = threadIdx.x & 31, ty = threadIdx.x >> 5;

    #pragma unroll
    for (int j = 0; j < 4; j++) {
        int kr = ty + j * 8;
        s[kr][tx] = Wp[(size_t)(k0 + kr) * D_SZ + n0 + tx] * scale;
    }
    __syncthreads();

    __half* outp = g_Wh + (size_t)sel * D_SZ * D_SZ;
    #pragma unroll
    for (int j = 0; j < 2; j++) {
        int idx = threadIdx.x + 256 * j;              // 512 half2 outputs
        int nc = idx >> 4, pe = (idx & 15) << 1;      // even kr in [0,32)
        int slot = (pe & ~15) + slot_e(pe & 15);
        __half2 val = __floats2half2_rn(s[pe][nc], s[pe + 1][nc]);
        *(__half2*)(outp + (size_t)(n0 + nc) * D_SZ + k0 + slot) = val;
    }
}

// ---------------------------------------------------------------------------
// Projection (fp16 m16n8k16): 128x128 tile, K-chunks of 64, double-buffered.
// A = X rows (m), B = W^T rows (n); both fragment loads are LDS.64.
// Epilogue writes Q/K as fp16 with the attention k16 permutation on d; V fp32.
// ---------------------------------------------------------------------------
#define PROJH_SMEM (2 * 2 * 128 * KSTR * 2)   // 2 tiles x 2 bufs x 128 x 80 halves
__global__ __launch_bounds__(256, 2) void proj_mma(const float* __restrict__ bq,
                                                   const float* __restrict__ bk,
                                                   const float* __restrict__ bv) {
    extern __shared__ char smc[];
    __half (*Xs)[128][KSTR] = (__half(*)[128][KSTR])smc;
    __half (*Ws)[128][KSTR] = (__half(*)[128][KSTR])(smc + 2 * 128 * KSTR * 2);

    const int tid = threadIdx.x, lane = tid & 31, wid = tid >> 5;
    const int wm = wid >> 1, wn = wid & 1;
    const int g = lane >> 2, t = lane & 3;
    const int n0 = blockIdx.x * 128, m0 = blockIdx.y * 128, sel = blockIdx.z;
    const __half* Xp = g_Xh;
    const __half* Wp = g_Wh + (size_t)sel * D_SZ * D_SZ;
    const float* bias = (sel == 0) ? bq : (sel == 1) ? bk : bv;

    uint32_t xs_b = (uint32_t)__cvta_generic_to_shared(&Xs[0][0][0]);
    uint32_t ws_b = (uint32_t)__cvta_generic_to_shared(&Ws[0][0][0]);

    auto issue = [&](int chunk, int buf) {
        int k0 = chunk * 64;
        #pragma unroll
        for (int i = tid; i < 1024; i += 256) {   // X tile: 128 rows x 64 halves
            int r = i >> 3, c8 = (i & 7) << 3;
            cpa16(xs_b + ((buf * 128 + r) * KSTR + c8) * 2, Xp + (size_t)(m0 + r) * D_SZ + k0 + c8);
        }
        #pragma unroll
        for (int i = tid; i < 1024; i += 256) {   // W^T tile: 128 rows x 64 halves
            int r = i >> 3, c8 = (i & 7) << 3;
            cpa16(ws_b + ((buf * 128 + r) * KSTR + c8) * 2, Wp + (size_t)(n0 + r) * D_SZ + k0 + c8);
        }
        cp_commit();
    };

    float acc[2][8][4] = {};
    issue(0, 0);

    for (int i = 0; i < 16; i++) {
        int buf = i & 1;
        if (i + 1 < 16) { issue(i + 1, 1 - buf); cp_wait<1>(); }
        else cp_wait<0>();
        __syncthreads();

        #pragma unroll
        for (int k16 = 0; k16 < 4; k16++) {
            int kk = k16 * 16 + 4 * t;
            unsigned a[2][4], b[8][2];
            #pragma unroll
            for (int mi = 0; mi < 2; mi++) {
                int rr = wm * 32 + mi * 16;
                uint2 w0 = *(const uint2*)&Xs[buf][rr + g][kk];
                uint2 w1 = *(const uint2*)&Xs[buf][rr + g + 8][kk];
                a[mi][0] = w0.x; a[mi][1] = w1.x; a[mi][2] = w0.y; a[mi][3] = w1.y;
            }
            #pragma unroll
            for (int nj = 0; nj < 8; nj++) {
                int cc = wn * 64 + nj * 8;
                uint2 wb = *(const uint2*)&Ws[buf][cc + g][kk];
                b[nj][0] = wb.x; b[nj][1] = wb.y;
            }
            #pragma unroll
            for (int mi = 0; mi < 2; mi++)
                #pragma unroll
                for (int nj = 0; nj < 8; nj++)
                    mma16h(acc[mi][nj], a[mi], b[nj]);
        }
        __syncthreads();
    }

    #pragma unroll
    for (int mi = 0; mi < 2; mi++) {
        int row = m0 + wm * 32 + mi * 16 + g;
        int bb = row >> 11, s = row & (S_SZ - 1);
        #pragma unroll
        for (int nj = 0; nj < 8; nj++) {
            int col = n0 + wn * 64 + nj * 8 + 2 * t;
            int h = col >> 6, d = col & 63;
            float bs = (sel == 0) ? KLOG : 1.0f;
            float b0 = bias[col] * bs, b1 = bias[col + 1] * bs;
            float v0 = acc[mi][nj][0] + b0, v1 = acc[mi][nj][1] + b1;
            float v2 = acc[mi][nj][2] + b0, v3 = acc[mi][nj][3] + b1;
            size_t base0 = ((size_t)(bb * H_SZ + h) * S_SZ + s) * HD_SZ;
            size_t base1 = ((size_t)(bb * H_SZ + h) * S_SZ + s + 8) * HD_SZ;
            if (sel == 2) {
                *(float2*)(g_V + base0 + d) = make_float2(v0, v1);
                *(float2*)(g_V + base1 + d) = make_float2(v2, v3);
            } else {
                __half* hp = (sel == 0) ? g_Qh : g_Kh;
                size_t o = (d & ~15) + slot_e(d & 15);
                *(__half2*)(hp + base0 + o) = __floats2half2_rn(v0, v1);
                *(__half2*)(hp + base1 + o) = __floats2half2_rn(v2, v3);
            }
        }
    }
}

// ---------------------------------------------------------------------------
// Pass A (lse): resident A = Q' (128 q-rows, fp16), streamed B = K (fp16).
// ---------------------------------------------------------------------------
#define LSE_SMEM (128 * KSTR * 2 + 2 * 128 * KSTR * 2 + 2 * 128 * 4)
__global__ __launch_bounds__(256, 2) void lse_mma() {
    extern __shared__ char smc[];
    __half (*Qs)[KSTR] = (__half(*)[KSTR])smc;
    __half (*Ks)[128][KSTR] = (__half(*)[128][KSTR])(smc + 128 * KSTR * 2);
    float (*red)[128] = (float(*)[128])(smc + 128 * KSTR * 2 + 2 * 128 * KSTR * 2);

    const int tid = threadIdx.x, lane = tid & 31, wid = tid >> 5;
    const int wm = wid >> 1, wn = wid & 1;
    const int g = lane >> 2, t = lane & 3;
    const int bh = blockIdx.y, q0 = blockIdx.x * 128;
    const __half* Qp = g_Qh + (size_t)bh * S_SZ * HD_SZ;
    const __half* Kp = g_Kh + (size_t)bh * S_SZ * HD_SZ;

    uint32_t qs_b = (uint32_t)__cvta_generic_to_shared(&Qs[0][0]);
    uint32_t ks_b = (uint32_t)__cvta_generic_to_shared(&Ks[0][0][0]);

    #pragma unroll
    for (int i = tid; i < 1024; i += 256) {
        int r = i >> 3, c8 = (i & 7) << 3;
        cpa16(qs_b + (r * KSTR + c8) * 2, Qp + (size_t)(q0 + r) * HD_SZ + c8);
    }
    cp_commit();

    auto issue = [&](int ktile, int buf) {
        int n0 = ktile * 128;
        #pragma unroll
        for (int i = tid; i < 1024; i += 256) {
            int r = i >> 3, c8 = (i & 7) << 3;
            cpa16(ks_b + ((buf * 128 + r) * KSTR + c8) * 2, Kp + (size_t)(n0 + r) * HD_SZ + c8);
        }
        cp_commit();
    };

    issue(0, 0);
    cp_wait<0>();
    __syncthreads();

    float rs[2][2] = {};

    for (int i = 0; i < 16; i++) {
        int buf = i & 1;
        if (i + 1 < 16) { issue(i + 1, 1 - buf); cp_wait<1>(); }
        else cp_wait<0>();
        __syncthreads();

        float acc[2][8][4] = {};
        #pragma unroll
        for (int k16 = 0; k16 < 4; k16++) {
            int kk = k16 * 16 + 4 * t;
            unsigned a[2][4], b[8][2];
            #pragma unroll
            for (int mi = 0; mi < 2; mi++) {
                int rr = wm * 32 + mi * 16;
                uint2 w0 = *(const uint2*)&Qs[rr + g][kk];
                uint2 w1 = *(const uint2*)&Qs[rr + g + 8][kk];
                a[mi][0] = w0.x; a[mi][1] = w1.x; a[mi][2] = w0.y; a[mi][3] = w1.y;
            }
            #pragma unroll
            for (int nj = 0; nj < 8; nj++) {
                int cc = wn * 64 + nj * 8;
                uint2 wb = *(const uint2*)&Ks[buf][cc + g][kk];
                b[nj][0] = wb.x; b[nj][1] = wb.y;
            }
            #pragma unroll
            for (int mi = 0; mi < 2; mi++)
                #pragma unroll
                for (int nj = 0; nj < 8; nj++)
                    mma16h(acc[mi][nj], a[mi], b[nj]);
        }

        #pragma unroll
        for (int mi = 0; mi < 2; mi++)
            #pragma unroll
            for (int nj = 0; nj < 8; nj++) {
                rs[mi][0] += ex2(acc[mi][nj][0]) + ex2(acc[mi][nj][1]);
                rs[mi][1] += ex2(acc[mi][nj][2]) + ex2(acc[mi][nj][3]);
            }
        __syncthreads();
    }

    #pragma unroll
    for (int mi = 0; mi < 2; mi++)
        #pragma unroll
        for (int h2 = 0; h2 < 2; h2++) {
            float v = rs[mi][h2];
            v += __shfl_xor_sync(0xffffffffu, v, 1);
            v += __shfl_xor_sync(0xffffffffu, v, 2);
            if (t == 0) red[wn][wm * 32 + mi * 16 + g + 8 * h2] = v;
        }
    __syncthreads();
    if (tid < 128)
        g_Ri[bh * S_SZ + q0 + tid] = 1.0f / (red[0][tid] + red[1][tid]);
}

// ---------------------------------------------------------------------------
// Pass B (wk): resident A = K (128 keys, fp16), streamed B = Q' + Ri.
// ---------------------------------------------------------------------------
#define WK_SMEM (128 * KSTR * 2 + 2 * 128 * KSTR * 2 + 2 * 128 * 4 + 2 * 128 * 4)
__global__ __launch_bounds__(256, 2) void wk_mma() {
    extern __shared__ char smc[];
    __half (*Kr)[KSTR] = (__half(*)[KSTR])smc;
    __half (*Qs)[128][KSTR] = (__half(*)[128][KSTR])(smc + 128 * KSTR * 2);
    float (*rsm)[128] = (float(*)[128])(smc + 128 * KSTR * 2 + 2 * 128 * KSTR * 2);
    float (*red)[128] = (float(*)[128])(smc + 128 * KSTR * 2 + 2 * 128 * KSTR * 2 + 2 * 128 * 4);

    const int tid = threadIdx.x, lane = tid & 31, wid = tid >> 5;
    const int wm = wid >> 1, wn = wid & 1;
    const int g = lane >> 2, t = lane & 3;
    const int bh = blockIdx.y, k0 = blockIdx.x * 128;
    const __half* Qp = g_Qh + (size_t)bh * S_SZ * HD_SZ;
    const __half* Kp = g_Kh + (size_t)bh * S_SZ * HD_SZ;
    const float* Rp = g_Ri + bh * S_SZ;

    uint32_t kr_b = (uint32_t)__cvta_generic_to_shared(&Kr[0][0]);
    uint32_t qs_b = (uint32_t)__cvta_generic_to_shared(&Qs[0][0][0]);
    uint32_t rs_b = (uint32_t)__cvta_generic_to_shared(&rsm[0][0]);

    #pragma unroll
    for (int i = tid; i < 1024; i += 256) {
        int r = i >> 3, c8 = (i & 7) << 3;
        cpa16(kr_b + (r * KSTR + c8) * 2, Kp + (size_t)(k0 + r) * HD_SZ + c8);
    }
    cp_commit();

    auto issue = [&](int qtile, int buf) {
        int n0 = qtile * 128;
        #pragma unroll
        for (int i = tid; i < 1024; i += 256) {
            int r = i >> 3, c8 = (i & 7) << 3;
            cpa16(qs_b + ((buf * 128 + r) * KSTR + c8) * 2, Qp + (size_t)(n0 + r) * HD_SZ + c8);
        }
        if (tid < 32) cpa16(rs_b + (buf * 128 + tid * 4) * 4, Rp + n0 + tid * 4);
        cp_commit();
    };

    issue(0, 0);
    cp_wait<0>();
    __syncthreads();

    float rs[2][2] = {};

    for (int i = 0; i < 16; i++) {
        int buf = i & 1;
        if (i + 1 < 16) { issue(i + 1, 1 - buf); cp_wait<1>(); }
        else cp_wait<0>();
        __syncthreads();

        float acc[2][8][4] = {};
        #pragma unroll
        for (int k16 = 0; k16 < 4; k16++) {
            int kk = k16 * 16 + 4 * t;
            unsigned a[2][4], b[8][2];
            #pragma unroll
            for (int mi = 0; mi < 2; mi++) {
                int rr = wm * 32 + mi * 16;
                uint2 w0 = *(const uint2*)&Kr[rr + g][kk];
                uint2 w1 = *(const uint2*)&Kr[rr + g + 8][kk];
                a[mi][0] = w0.x; a[mi][1] = w1.x; a[mi][2] = w0.y; a[mi][3] = w1.y;
            }
            #pragma unroll
            for (int nj = 0; nj < 8; nj++) {
                int cc = wn * 64 + nj * 8;
                uint2 wb = *(const uint2*)&Qs[buf][cc + g][kk];
                b[nj][0] = wb.x; b[nj][1] = wb.y;
            }
            #pragma unroll
            for (int mi = 0; mi < 2; mi++)
                #pragma unroll
                for (int nj = 0; nj < 8; nj++)
                    mma16h(acc[mi][nj], a[mi], b[nj]);
        }

        #pragma unroll
        for (int nj = 0; nj < 8; nj++) {
            int cb = wn * 64 + nj * 8 + 2 * t;
            float r0 = rsm[buf][cb], r1 = rsm[buf][cb + 1];
            #pragma unroll
            for (int mi = 0; mi < 2; mi++) {
                rs[mi][0] = fmaf(ex2(acc[mi][nj][0]), r0, rs[mi][0]);
                rs[mi][0] = fmaf(ex2(acc[mi][nj][1]), r1, rs[mi][0]);
                rs[mi][1] = fmaf(ex2(acc[mi][nj][2]), r0, rs[mi][1]);
                rs[mi][1] = fmaf(ex2(acc[mi][nj][3]), r1, rs[mi][1]);
            }
        }
        __syncthreads();
    }

    #pragma unroll
    for (int mi = 0; mi < 2; mi++)
        #pragma unroll
        for (int h2 = 0; h2 < 2; h2++) {
            float v = rs[mi][h2];
            v += __shfl_xor_sync(0xffffffffu, v, 1);
            v += __shfl_xor_sync(0xffffffffu, v, 2);
            if (t == 0) red[wn][wm * 32 + mi * 16 + g + 8 * h2] = v;
        }
    __syncthreads();
    if (tid < 128)
        g_w[bh * S_SZ + k0 + tid] = (red[0][tid] + red[1][tid]) * (1.0f / S_SZ);
}

// ---------------------------------------------------------------------------
// Output: out[b, h*64+d] = sum_k w[bh,k] * V[bh,k,d]. One block per bh.
// ---------------------------------------------------------------------------
__global__ __launch_bounds__(256) void outk(float* __restrict__ out) {
    __shared__ float red2[4][64];
    const int bh = blockIdx.x, tid = threadIdx.x;
    const int d = tid & 63, sl = tid >> 6;
    const float* Vp = g_V + (size_t)bh * S_SZ * HD_SZ;
    const float* wp = g_w + bh * S_SZ;
    float a = 0.f;
    #pragma unroll 4
    for (int k = sl * 512; k < (sl + 1) * 512; ++k)
        a = fmaf(wp[k], Vp[(size_t)k * HD_SZ + d], a);
    red2[sl][d] = a;
    __syncthreads();
    if (tid < 64) {
        float s = red2[0][tid] + red2[1][tid] + red2[2][tid] + red2[3][tid];
        int bb = bh >> 4, h = bh & 15;
        out[bb * D_SZ + h * HD_SZ + tid] = s;
    }
}

// ---------------------------------------------------------------------------
extern "C" void kernel_launch(void* const* d_in, const int* in_sizes, int n_in,
                              void* d_out, int out_size) {
    (void)in_sizes; (void)n_in; (void)out_size;
    const float* X  = (const float*)d_in[0];
    const float* Wq = (const float*)d_in[1];
    const float* bq = (const float*)d_in[2];
    const float* Wk = (const float*)d_in[3];
    const float* bk = (const float*)d_in[4];
    const float* Wv = (const float*)d_in[5];
    const float* bv = (const float*)d_in[6];
    float* out = (float*)d_out;

    cudaFuncSetAttribute(proj_mma, cudaFuncAttributeMaxDynamicSharedMemorySize, PROJH_SMEM);
    cudaFuncSetAttribute(lse_mma,  cudaFuncAttributeMaxDynamicSharedMemorySize, LSE_SMEM);
    cudaFuncSetAttribute(wk_mma,   cudaFuncAttributeMaxDynamicSharedMemorySize, WK_SMEM);

    prep_x<<<1024, 256>>>(X);
    prep_w<<<dim3(32, 32, 3), 256>>>(Wq, Wk, Wv);

    dim3 gproj(D_SZ / 128, TOK_SZ / 128, 3);   // (8, 32, 3)
    proj_mma<<<gproj, 256, PROJH_SMEM>>>(bq, bk, bv);

    dim3 ga(S_SZ / 128, BH_SZ);                // (16, 32)
    lse_mma<<<ga, 256, LSE_SMEM>>>();
    wk_mma<<<ga, 256, WK_SMEM>>>();

    outk<<<BH_SZ, 256>>>(out);
}

// round 10
// speedup vs baseline: 1.7183x; 1.7183x over previous
#include <cuda_runtime.h>
#include <cuda_fp16.h>
#include <cstdint>

#define S_SZ 2048
#define D_SZ 1024
#define H_SZ 16
#define HD_SZ 64
#define B_SZ 2
#define BH_SZ (B_SZ * H_SZ)       // 32
#define TOK_SZ (B_SZ * S_SZ)      // 4096
#define KLOG 0.18033688011112042f // 0.125 * log2(e)
#define KSTR 72                   // halves per smem row (144B: LDSM conflict-free)

// Scratch (device globals: allocation-free rule)
__device__ __half g_Xh[TOK_SZ * D_SZ];        // fp16 X, natural order
__device__ __half g_Wh[3 * D_SZ * D_SZ];      // fp16 W^T [n][k]; Wq pre-scaled by KLOG
__device__ __half g_Qh[BH_SZ * S_SZ * HD_SZ]; // fp16 Q (KLOG-scaled), natural d
__device__ __half g_Kh[BH_SZ * S_SZ * HD_SZ]; // fp16 K, natural d
__device__ float  g_V[BH_SZ * S_SZ * HD_SZ];  // full fp32
__device__ float  g_Ri[BH_SZ * S_SZ];         // 1 / rowsum(exp2(scores2))
__device__ float  g_w[BH_SZ * S_SZ];          // mean attention weight per key

// ---------------------------------------------------------------------------
__device__ __forceinline__ void mma16h(float c[4], const unsigned a[4], const unsigned* b) {
    asm volatile(
        "mma.sync.aligned.m16n8k16.row.col.f32.f16.f16.f32 "
        "{%0,%1,%2,%3}, {%4,%5,%6,%7}, {%8,%9}, {%0,%1,%2,%3};\n"
        : "+f"(c[0]), "+f"(c[1]), "+f"(c[2]), "+f"(c[3])
        : "r"(a[0]), "r"(a[1]), "r"(a[2]), "r"(a[3]), "r"(b[0]), "r"(b[1]));
}

__device__ __forceinline__ void ldsm4(unsigned& r0, unsigned& r1, unsigned& r2, unsigned& r3,
                                      uint32_t addr) {
    asm volatile("ldmatrix.sync.aligned.m8n8.x4.shared.b16 {%0,%1,%2,%3}, [%4];"
                 : "=r"(r0), "=r"(r1), "=r"(r2), "=r"(r3) : "r"(addr));
}

// 2^x on the MUFU pipe (input already in log2 domain).
__device__ __forceinline__ float ex2(float x) {
    float y; asm("ex2.approx.f32 %0, %1;" : "=f"(y) : "f"(x)); return y;
}

__device__ __forceinline__ void cpa16(uint32_t dst, const void* src) {
    asm volatile("cp.async.ca.shared.global [%0], [%1], 16;\n" :: "r"(dst), "l"(src));
}
__device__ __forceinline__ void cp_commit() { asm volatile("cp.async.commit_group;\n"); }
template <int N> __device__ __forceinline__ void cp_wait() {
    asm volatile("cp.async.wait_group %0;\n" :: "n"(N));
}

// ---------------------------------------------------------------------------
// Prep X: straight fp16 convert (coalesced 16B stores).
// ---------------------------------------------------------------------------
__global__ __launch_bounds__(256) void prep_x(const float* __restrict__ X) {
    const int N8 = TOK_SZ * D_SZ / 8;
    int stride = gridDim.x * blockDim.x;
    for (int i = blockIdx.x * blockDim.x + threadIdx.x; i < N8; i += stride) {
        float4 v0 = ((const float4*)X)[2 * i];
        float4 v1 = ((const float4*)X)[2 * i + 1];
        __half2 h[4] = { __floats2half2_rn(v0.x, v0.y), __floats2half2_rn(v0.z, v0.w),
                         __floats2half2_rn(v1.x, v1.y), __floats2half2_rn(v1.z, v1.w) };
        *(uint4*)(g_Xh + (size_t)8 * i) = *(const uint4*)h;
    }
}

// ---------------------------------------------------------------------------
// Prep W: transpose to [n][k], fp16; fold KLOG into Wq. 32x32 tiles.
// ---------------------------------------------------------------------------
__global__ __launch_bounds__(256) void prep_w(const float* __restrict__ Wq,
                                              const float* __restrict__ Wk,
                                              const float* __restrict__ Wv) {
    __shared__ float s[32][33];
    const int sel = blockIdx.z;
    const int k0 = blockIdx.x * 32, n0 = blockIdx.y * 32;
    const float* Wp = (sel == 0) ? Wq : (sel == 1) ? Wk : Wv;
    const float scale = (sel == 0) ? KLOG : 1.0f;
    const int tx = threadIdx.x & 31, ty = threadIdx.x >> 5;

    #pragma unroll
    for (int j = 0; j < 4; j++) {
        int kr = ty + j * 8;
        s[kr][tx] = Wp[(size_t)(k0 + kr) * D_SZ + n0 + tx] * scale;
    }
    __syncthreads();

    __half* outp = g_Wh + (size_t)sel * D_SZ * D_SZ;
    #pragma unroll
    for (int j = 0; j < 2; j++) {
        int idx = threadIdx.x + 256 * j;              // 512 half2 outputs
        int nc = idx >> 4, pe = (idx & 15) << 1;
        __half2 val = __floats2half2_rn(s[pe][nc], s[pe + 1][nc]);
        *(__half2*)(outp + (size_t)(n0 + nc) * D_SZ + k0 + pe) = val;
    }
}

// ---------------------------------------------------------------------------
// Projection (fp16 m16n8k16, ldmatrix): 128x128 tile, K-chunks of 64,
// cp.async double-buffered. A = X rows, B = W^T rows.
// ---------------------------------------------------------------------------
#define PROJH_SMEM (4 * 128 * KSTR * 2)
__global__ __launch_bounds__(256, 2) void proj_mma(const float* __restrict__ bq,
                                                   const float* __restrict__ bk,
                                                   const float* __restrict__ bv) {
    extern __shared__ char smc[];
    const int TB = 128 * KSTR * 2;                // bytes per tile buffer
    __half* Xs = (__half*)smc;                    // 2 buffers
    __half* Ws = (__half*)(smc + 2 * TB);         // 2 buffers

    const int tid = threadIdx.x, lane = tid & 31, wid = tid >> 5;
    const int wm = wid >> 1, wn = wid & 1;
    const int g = lane >> 2, t = lane & 3;
    const int n0 = blockIdx.x * 128, m0 = blockIdx.y * 128, sel = blockIdx.z;
    const __half* Xp = g_Xh;
    const __half* Wp = g_Wh + (size_t)sel * D_SZ * D_SZ;
    const float* bias = (sel == 0) ? bq : (sel == 1) ? bk : bv;

    uint32_t xs_b = (uint32_t)__cvta_generic_to_shared(Xs);
    uint32_t ws_b = (uint32_t)__cvta_generic_to_shared(Ws);

    // per-lane ldmatrix offsets (halves within a buffer)
    const int la = lane & 15, ha = lane >> 4;
    const int lbr = (lane & 7) + 8 * (lane >> 4);
    const int lbc = ((lane >> 3) & 1) * 8;
    uint32_t aoff[2], boff[4];
    #pragma unroll
    for (int mi = 0; mi < 2; mi++)
        aoff[mi] = ((wm * 32 + mi * 16 + la) * KSTR + 8 * ha) * 2;
    #pragma unroll
    for (int njp = 0; njp < 4; njp++)
        boff[njp] = ((wn * 64 + njp * 16 + lbr) * KSTR + lbc) * 2;

    auto issue = [&](int chunk, int buf) {
        int k0 = chunk * 64;
        #pragma unroll
        for (int i = tid; i < 1024; i += 256) {
            int r = i >> 3, c8 = (i & 7) << 3;
            cpa16(xs_b + buf * TB + (r * KSTR + c8) * 2, Xp + (size_t)(m0 + r) * D_SZ + k0 + c8);
        }
        #pragma unroll
        for (int i = tid; i < 1024; i += 256) {
            int r = i >> 3, c8 = (i & 7) << 3;
            cpa16(ws_b + buf * TB + (r * KSTR + c8) * 2, Wp + (size_t)(n0 + r) * D_SZ + k0 + c8);
        }
        cp_commit();
    };

    float acc[2][8][4] = {};
    issue(0, 0);

    for (int i = 0; i < 16; i++) {
        int buf = i & 1;
        if (i + 1 < 16) { issue(i + 1, 1 - buf); cp_wait<1>(); }
        else cp_wait<0>();
        __syncthreads();

        #pragma unroll
        for (int k16 = 0; k16 < 4; k16++) {
            unsigned a[2][4], b[4][4];
            #pragma unroll
            for (int mi = 0; mi < 2; mi++)
                ldsm4(a[mi][0], a[mi][1], a[mi][2], a[mi][3],
                      xs_b + buf * TB + aoff[mi] + k16 * 32);
            #pragma unroll
            for (int njp = 0; njp < 4; njp++)
                ldsm4(b[njp][0], b[njp][1], b[njp][2], b[njp][3],
                      ws_b + buf * TB + boff[njp] + k16 * 32);
            #pragma unroll
            for (int mi = 0; mi < 2; mi++)
                #pragma unroll
                for (int nj = 0; nj < 8; nj++)
                    mma16h(acc[mi][nj], a[mi], &b[nj >> 1][2 * (nj & 1)]);
        }
        __syncthreads();
    }

    #pragma unroll
    for (int mi = 0; mi < 2; mi++) {
        int row = m0 + wm * 32 + mi * 16 + g;
        int bb = row >> 11, s = row & (S_SZ - 1);
        #pragma unroll
        for (int nj = 0; nj < 8; nj++) {
            int col = n0 + wn * 64 + nj * 8 + 2 * t;
            int h = col >> 6, d = col & 63;
            float bs = (sel == 0) ? KLOG : 1.0f;
            float b0 = bias[col] * bs, b1 = bias[col + 1] * bs;
            float v0 = acc[mi][nj][0] + b0, v1 = acc[mi][nj][1] + b1;
            float v2 = acc[mi][nj][2] + b0, v3 = acc[mi][nj][3] + b1;
            size_t base0 = ((size_t)(bb * H_SZ + h) * S_SZ + s) * HD_SZ;
            size_t base1 = ((size_t)(bb * H_SZ + h) * S_SZ + s + 8) * HD_SZ;
            if (sel == 2) {
                *(float2*)(g_V + base0 + d) = make_float2(v0, v1);
                *(float2*)(g_V + base1 + d) = make_float2(v2, v3);
            } else {
                __half* hp = (sel == 0) ? g_Qh : g_Kh;
                *(__half2*)(hp + base0 + d) = __floats2half2_rn(v0, v1);
                *(__half2*)(hp + base1 + d) = __floats2half2_rn(v2, v3);
            }
        }
    }
}

// ---------------------------------------------------------------------------
// Pass A (lse): resident A = Q' (128 q-rows), streamed B = K. ldmatrix loads.
// ---------------------------------------------------------------------------
#define LSE_SMEM (3 * 128 * KSTR * 2 + 2 * 128 * 4)
__global__ __launch_bounds__(256, 2) void lse_mma() {
    extern __shared__ char smc[];
    const int TB = 128 * KSTR * 2;
    __half* Qs = (__half*)smc;                     // resident
    __half* Ks = (__half*)(smc + TB);              // 2 buffers
    float (*red)[128] = (float(*)[128])(smc + 3 * TB);

    const int tid = threadIdx.x, lane = tid & 31, wid = tid >> 5;
    const int wm = wid >> 1, wn = wid & 1;
    const int g = lane >> 2, t = lane & 3;
    const int bh = blockIdx.y, q0 = blockIdx.x * 128;
    const __half* Qp = g_Qh + (size_t)bh * S_SZ * HD_SZ;
    const __half* Kp = g_Kh + (size_t)bh * S_SZ * HD_SZ;

    uint32_t qs_b = (uint32_t)__cvta_generic_to_shared(Qs);
    uint32_t ks_b = (uint32_t)__cvta_generic_to_shared(Ks);

    const int la = lane & 15, ha = lane >> 4;
    const int lbr = (lane & 7) + 8 * (lane >> 4);
    const int lbc = ((lane >> 3) & 1) * 8;
    uint32_t aoff[2], boff[4];
    #pragma unroll
    for (int mi = 0; mi < 2; mi++)
        aoff[mi] = qs_b + ((wm * 32 + mi * 16 + la) * KSTR + 8 * ha) * 2;
    #pragma unroll
    for (int njp = 0; njp < 4; njp++)
        boff[njp] = ((wn * 64 + njp * 16 + lbr) * KSTR + lbc) * 2;

    #pragma unroll
    for (int i = tid; i < 1024; i += 256) {
        int r = i >> 3, c8 = (i & 7) << 3;
        cpa16(qs_b + (r * KSTR + c8) * 2, Qp + (size_t)(q0 + r) * HD_SZ + c8);
    }
    cp_commit();

    auto issue = [&](int ktile, int buf) {
        int n0 = ktile * 128;
        #pragma unroll
        for (int i = tid; i < 1024; i += 256) {
            int r = i >> 3, c8 = (i & 7) << 3;
            cpa16(ks_b + buf * TB + (r * KSTR + c8) * 2, Kp + (size_t)(n0 + r) * HD_SZ + c8);
        }
        cp_commit();
    };

    issue(0, 0);
    cp_wait<0>();
    __syncthreads();

    float rs[2][2] = {};

    for (int i = 0; i < 16; i++) {
        int buf = i & 1;
        if (i + 1 < 16) { issue(i + 1, 1 - buf); cp_wait<1>(); }
        else cp_wait<0>();
        __syncthreads();

        float acc[2][8][4] = {};
        #pragma unroll
        for (int k16 = 0; k16 < 4; k16++) {
            unsigned a[2][4], b[4][4];
            #pragma unroll
            for (int mi = 0; mi < 2; mi++)
                ldsm4(a[mi][0], a[mi][1], a[mi][2], a[mi][3], aoff[mi] + k16 * 32);
            #pragma unroll
            for (int njp = 0; njp < 4; njp++)
                ldsm4(b[njp][0], b[njp][1], b[njp][2], b[njp][3],
                      ks_b + buf * TB + boff[njp] + k16 * 32);
            #pragma unroll
            for (int mi = 0; mi < 2; mi++)
                #pragma unroll
                for (int nj = 0; nj < 8; nj++)
                    mma16h(acc[mi][nj], a[mi], &b[nj >> 1][2 * (nj & 1)]);
        }

        #pragma unroll
        for (int mi = 0; mi < 2; mi++)
            #pragma unroll
            for (int nj = 0; nj < 8; nj++) {
                rs[mi][0] += ex2(acc[mi][nj][0]) + ex2(acc[mi][nj][1]);
                rs[mi][1] += ex2(acc[mi][nj][2]) + ex2(acc[mi][nj][3]);
            }
        __syncthreads();
    }

    #pragma unroll
    for (int mi = 0; mi < 2; mi++)
        #pragma unroll
        for (int h2 = 0; h2 < 2; h2++) {
            float v = rs[mi][h2];
            v += __shfl_xor_sync(0xffffffffu, v, 1);
            v += __shfl_xor_sync(0xffffffffu, v, 2);
            if (t == 0) red[wn][wm * 32 + mi * 16 + g + 8 * h2] = v;
        }
    __syncthreads();
    if (tid < 128)
        g_Ri[bh * S_SZ + q0 + tid] = 1.0f / (red[0][tid] + red[1][tid]);
}

// ---------------------------------------------------------------------------
// Pass B (wk): resident A = K (128 keys), streamed B = Q' + Ri.
// ---------------------------------------------------------------------------
#define WK_SMEM (3 * 128 * KSTR * 2 + 2 * 128 * 4 + 2 * 128 * 4)
__global__ __launch_bounds__(256, 2) void wk_mma() {
    extern __shared__ char smc[];
    const int TB = 128 * KSTR * 2;
    __half* Kr = (__half*)smc;
    __half* Qs = (__half*)(smc + TB);
    float (*rsm)[128] = (float(*)[128])(smc + 3 * TB);
    float (*red)[128] = (float(*)[128])(smc + 3 * TB + 2 * 128 * 4);

    const int tid = threadIdx.x, lane = tid & 31, wid = tid >> 5;
    const int wm = wid >> 1, wn = wid & 1;
    const int g = lane >> 2, t = lane & 3;
    const int bh = blockIdx.y, k0 = blockIdx.x * 128;
    const __half* Qp = g_Qh + (size_t)bh * S_SZ * HD_SZ;
    const __half* Kp = g_Kh + (size_t)bh * S_SZ * HD_SZ;
    const float* Rp = g_Ri + bh * S_SZ;

    uint32_t kr_b = (uint32_t)__cvta_generic_to_shared(Kr);
    uint32_t qs_b = (uint32_t)__cvta_generic_to_shared(Qs);
    uint32_t rs_b = (uint32_t)__cvta_generic_to_shared(&rsm[0][0]);

    const int la = lane & 15, ha = lane >> 4;
    const int lbr = (lane & 7) + 8 * (lane >> 4);
    const int lbc = ((lane >> 3) & 1) * 8;
    uint32_t aoff[2], boff[4];
    #pragma unroll
    for (int mi = 0; mi < 2; mi++)
        aoff[mi] = kr_b + ((wm * 32 + mi * 16 + la) * KSTR + 8 * ha) * 2;
    #pragma unroll
    for (int njp = 0; njp < 4; njp++)
        boff[njp] = ((wn * 64 + njp * 16 + lbr) * KSTR + lbc) * 2;

    #pragma unroll
    for (int i = tid; i < 1024; i += 256) {
        int r = i >> 3, c8 = (i & 7) << 3;
        cpa16(kr_b + (r * KSTR + c8) * 2, Kp + (size_t)(k0 + r) * HD_SZ + c8);
    }
    cp_commit();

    auto issue = [&](int qtile, int buf) {
        int n0 = qtile * 128;
        #pragma unroll
        for (int i = tid; i < 1024; i += 256) {
            int r = i >> 3, c8 = (i & 7) << 3;
            cpa16(qs_b + buf * TB + (r * KSTR + c8) * 2, Qp + (size_t)(n0 + r) * HD_SZ + c8);
        }
        if (tid < 32) cpa16(rs_b + (buf * 128 + tid * 4) * 4, Rp + n0 + tid * 4);
        cp_commit();
    };

    issue(0, 0);
    cp_wait<0>();
    __syncthreads();

    float rs[2][2] = {};

    for (int i = 0; i < 16; i++) {
        int buf = i & 1;
        if (i + 1 < 16) { issue(i + 1, 1 - buf); cp_wait<1>(); }
        else cp_wait<0>();
        __syncthreads();

        float acc[2][8][4] = {};
        #pragma unroll
        for (int k16 = 0; k16 < 4; k16++) {
            unsigned a[2][4], b[4][4];
            #pragma unroll
            for (int mi = 0; mi < 2; mi++)
                ldsm4(a[mi][0], a[mi][1], a[mi][2], a[mi][3], aoff[mi] + k16 * 32);
            #pragma unroll
            for (int njp = 0; njp < 4; njp++)
                ldsm4(b[njp][0], b[njp][1], b[njp][2], b[njp][3],
                      qs_b + buf * TB + boff[njp] + k16 * 32);
            #pragma unroll
            for (int mi = 0; mi < 2; mi++)
                #pragma unroll
                for (int nj = 0; nj < 8; nj++)
                    mma16h(acc[mi][nj], a[mi], &b[nj >> 1][2 * (nj & 1)]);
        }

        #pragma unroll
        for (int nj = 0; nj < 8; nj++) {
            int cb = wn * 64 + nj * 8 + 2 * t;
            float r0 = rsm[buf][cb], r1 = rsm[buf][cb + 1];
            #pragma unroll
            for (int mi = 0; mi < 2; mi++) {
                rs[mi][0] = fmaf(ex2(acc[mi][nj][0]), r0, rs[mi][0]);
                rs[mi][0] = fmaf(ex2(acc[mi][nj][1]), r1, rs[mi][0]);
                rs[mi][1] = fmaf(ex2(acc[mi][nj][2]), r0, rs[mi][1]);
                rs[mi][1] = fmaf(ex2(acc[mi][nj][3]), r1, rs[mi][1]);
            }
        }
        __syncthreads();
    }

    #pragma unroll
    for (int mi = 0; mi < 2; mi++)
        #pragma unroll
        for (int h2 = 0; h2 < 2; h2++) {
            float v = rs[mi][h2];
            v += __shfl_xor_sync(0xffffffffu, v, 1);
            v += __shfl_xor_sync(0xffffffffu, v, 2);
            if (t == 0) red[wn][wm * 32 + mi * 16 + g + 8 * h2] = v;
        }
    __syncthreads();
    if (tid < 128)
        g_w[bh * S_SZ + k0 + tid] = (red[0][tid] + red[1][tid]) * (1.0f / S_SZ);
}

// ---------------------------------------------------------------------------
// Output: out[b, h*64+d] = sum_k w[bh,k] * V[bh,k,d]. One block per bh.
// ---------------------------------------------------------------------------
__global__ __launch_bounds__(256) void outk(float* __restrict__ out) {
    __shared__ float red2[4][64];
    const int bh = blockIdx.x, tid = threadIdx.x;
    const int d = tid & 63, sl = tid >> 6;
    const float* Vp = g_V + (size_t)bh * S_SZ * HD_SZ;
    const float* wp = g_w + bh * S_SZ;
    float a = 0.f;
    #pragma unroll 4
    for (int k = sl * 512; k < (sl + 1) * 512; ++k)
        a = fmaf(wp[k], Vp[(size_t)k * HD_SZ + d], a);
    red2[sl][d] = a;
    __syncthreads();
    if (tid < 64) {
        float s = red2[0][tid] + red2[1][tid] + red2[2][tid] + red2[3][tid];
        int bb = bh >> 4, h = bh & 15;
        out[bb * D_SZ + h * HD_SZ + tid] = s;
    }
}

// ---------------------------------------------------------------------------
extern "C" void kernel_launch(void* const* d_in, const int* in_sizes, int n_in,
                              void* d_out, int out_size) {
    (void)in_sizes; (void)n_in; (void)out_size;
    const float* X  = (const float*)d_in[0];
    const float* Wq = (const float*)d_in[1];
    const float* bq = (const float*)d_in[2];
    const float* Wk = (const float*)d_in[3];
    const float* bk = (const float*)d_in[4];
    const float* Wv = (const float*)d_in[5];
    const float* bv = (const float*)d_in[6];
    float* out = (float*)d_out;

    cudaFuncSetAttribute(proj_mma, cudaFuncAttributeMaxDynamicSharedMemorySize, PROJH_SMEM);
    cudaFuncSetAttribute(lse_mma,  cudaFuncAttributeMaxDynamicSharedMemorySize, LSE_SMEM);
    cudaFuncSetAttribute(wk_mma,   cudaFuncAttributeMaxDynamicSharedMemorySize, WK_SMEM);

    prep_x<<<1024, 256>>>(X);
    prep_w<<<dim3(32, 32, 3), 256>>>(Wq, Wk, Wv);

    dim3 gproj(D_SZ / 128, TOK_SZ / 128, 3);   // (8, 32, 3)
    proj_mma<<<gproj, 256, PROJH_SMEM>>>(bq, bk, bv);

    dim3 ga(S_SZ / 128, BH_SZ);                // (16, 32)
    lse_mma<<<ga, 256, LSE_SMEM>>>();
    wk_mma<<<ga, 256, WK_SMEM>>>();

    outk<<<BH_SZ, 256>>>(out);
}

// round 12
// speedup vs baseline: 1.8358x; 1.0684x over previous
#include <cuda_runtime.h>
#include <cuda_fp16.h>
#include <cstdint>

#define S_SZ 2048
#define D_SZ 1024
#define H_SZ 16
#define HD_SZ 64
#define B_SZ 2
#define BH_SZ (B_SZ * H_SZ)       // 32
#define TOK_SZ (B_SZ * S_SZ)      // 4096
#define KLOG 0.18033688011112042f // 0.125 * log2(e)
#define KSTR 72                   // halves per smem row (144B: LDSM conflict-free)

// Scratch (device globals: allocation-free rule)
__device__ __half g_Xh[TOK_SZ * D_SZ];        // fp16 X, natural order
__device__ __half g_Wh[3 * D_SZ * D_SZ];      // fp16 W^T [n][k]; Wq pre-scaled by KLOG
__device__ __half g_Qh[BH_SZ * S_SZ * HD_SZ]; // fp16 Q (KLOG-scaled), natural d
__device__ __half g_Kh[BH_SZ * S_SZ * HD_SZ]; // fp16 K, natural d
__device__ float  g_V[BH_SZ * S_SZ * HD_SZ];  // full fp32
__device__ float  g_Ri[BH_SZ * S_SZ];         // 1 / rowsum(exp2(scores2))
__device__ float  g_w[BH_SZ * S_SZ];          // mean attention weight per key

// ---------------------------------------------------------------------------
__device__ __forceinline__ void mma16h(float c[4], const unsigned a[4], const unsigned* b) {
    asm volatile(
        "mma.sync.aligned.m16n8k16.row.col.f32.f16.f16.f32 "
        "{%0,%1,%2,%3}, {%4,%5,%6,%7}, {%8,%9}, {%0,%1,%2,%3};\n"
        : "+f"(c[0]), "+f"(c[1]), "+f"(c[2]), "+f"(c[3])
        : "r"(a[0]), "r"(a[1]), "r"(a[2]), "r"(a[3]), "r"(b[0]), "r"(b[1]));
}

__device__ __forceinline__ void ldsm4(unsigned& r0, unsigned& r1, unsigned& r2, unsigned& r3,
                                      uint32_t addr) {
    asm volatile("ldmatrix.sync.aligned.m8n8.x4.shared.b16 {%0,%1,%2,%3}, [%4];"
                 : "=r"(r0), "=r"(r1), "=r"(r2), "=r"(r3) : "r"(addr));
}

// two exp2 per MUFU op
__device__ __forceinline__ __half2 h2ex2(__half2 x) {
    unsigned xi = *reinterpret_cast<unsigned*>(&x), yi;
    asm("ex2.approx.f16x2 %0, %1;" : "=r"(yi) : "r"(xi));
    return *reinterpret_cast<__half2*>(&yi);
}

__device__ __forceinline__ void cpa16(uint32_t dst, const void* src) {
    asm volatile("cp.async.ca.shared.global [%0], [%1], 16;\n" :: "r"(dst), "l"(src));
}
__device__ __forceinline__ void cp_commit() { asm volatile("cp.async.commit_group;\n"); }
template <int N> __device__ __forceinline__ void cp_wait() {
    asm volatile("cp.async.wait_group %0;\n" :: "n"(N));
}

// ---------------------------------------------------------------------------
// Prep (fused): blocks [0,1024) convert X to fp16; blocks [1024,4096) build
// fp16 W^T with KLOG folded into Wq.
// ---------------------------------------------------------------------------
__global__ __launch_bounds__(256) void prep_all(const float* __restrict__ X,
                                                const float* __restrict__ Wq,
                                                const float* __restrict__ Wk,
                                                const float* __restrict__ Wv) {
    __shared__ float s[32][33];
    const int bx = blockIdx.x, tid = threadIdx.x;
    if (bx < 1024) {
        const int N8 = TOK_SZ * D_SZ / 8;
        for (int i = bx * 256 + tid; i < N8; i += 1024 * 256) {
            float4 v0 = ((const float4*)X)[2 * i];
            float4 v1 = ((const float4*)X)[2 * i + 1];
            __half2 h[4] = { __floats2half2_rn(v0.x, v0.y), __floats2half2_rn(v0.z, v0.w),
                             __floats2half2_rn(v1.x, v1.y), __floats2half2_rn(v1.z, v1.w) };
            *(uint4*)(g_Xh + (size_t)8 * i) = *(const uint4*)h;
        }
        return;
    }
    const int idx = bx - 1024;
    const int sel = idx >> 10, rem = idx & 1023;
    const int k0 = (rem & 31) * 32, n0 = (rem >> 5) * 32;
    const float* Wp = (sel == 0) ? Wq : (sel == 1) ? Wk : Wv;
    const float scale = (sel == 0) ? KLOG : 1.0f;
    const int tx = tid & 31, ty = tid >> 5;

    #pragma unroll
    for (int j = 0; j < 4; j++) {
        int kr = ty + j * 8;
        s[kr][tx] = Wp[(size_t)(k0 + kr) * D_SZ + n0 + tx] * scale;
    }
    __syncthreads();

    __half* outp = g_Wh + (size_t)sel * D_SZ * D_SZ;
    #pragma unroll
    for (int j = 0; j < 2; j++) {
        int i2 = tid + 256 * j;
        int nc = i2 >> 4, pe = (i2 & 15) << 1;
        __half2 val = __floats2half2_rn(s[pe][nc], s[pe + 1][nc]);
        *(__half2*)(outp + (size_t)(n0 + nc) * D_SZ + k0 + pe) = val;
    }
}

// ---------------------------------------------------------------------------
// Projection body (fp16 m16n8k16, ldmatrix): 128x128 tile, K-chunks of 64.
// ---------------------------------------------------------------------------
#define PROJH_SMEM (4 * 128 * KSTR * 2)
__device__ __forceinline__ void proj_body(int sel, int n0, int m0, const float* bias) {
    extern __shared__ char smc[];
    const int TB = 128 * KSTR * 2;
    __half* Xs = (__half*)smc;
    __half* Ws = (__half*)(smc + 2 * TB);

    const int tid = threadIdx.x, lane = tid & 31, wid = tid >> 5;
    const int wm = wid >> 1, wn = wid & 1;
    const int g = lane >> 2, t = lane & 3;
    const __half* Xp = g_Xh;
    const __half* Wp = g_Wh + (size_t)sel * D_SZ * D_SZ;

    uint32_t xs_b = (uint32_t)__cvta_generic_to_shared(Xs);
    uint32_t ws_b = (uint32_t)__cvta_generic_to_shared(Ws);

    const int la = lane & 15, ha = lane >> 4;
    const int lbr = (lane & 7) + 8 * (lane >> 4);
    const int lbc = ((lane >> 3) & 1) * 8;
    uint32_t aoff[2], boff[4];
    #pragma unroll
    for (int mi = 0; mi < 2; mi++)
        aoff[mi] = ((wm * 32 + mi * 16 + la) * KSTR + 8 * ha) * 2;
    #pragma unroll
    for (int njp = 0; njp < 4; njp++)
        boff[njp] = ((wn * 64 + njp * 16 + lbr) * KSTR + lbc) * 2;

    auto issue = [&](int chunk, int buf) {
        int k0 = chunk * 64;
        #pragma unroll
        for (int i = tid; i < 1024; i += 256) {
            int r = i >> 3, c8 = (i & 7) << 3;
            cpa16(xs_b + buf * TB + (r * KSTR + c8) * 2, Xp + (size_t)(m0 + r) * D_SZ + k0 + c8);
        }
        #pragma unroll
        for (int i = tid; i < 1024; i += 256) {
            int r = i >> 3, c8 = (i & 7) << 3;
            cpa16(ws_b + buf * TB + (r * KSTR + c8) * 2, Wp + (size_t)(n0 + r) * D_SZ + k0 + c8);
        }
        cp_commit();
    };

    float acc[2][8][4] = {};
    issue(0, 0);

    for (int i = 0; i < 16; i++) {
        int buf = i & 1;
        if (i + 1 < 16) { issue(i + 1, 1 - buf); cp_wait<1>(); }
        else cp_wait<0>();
        __syncthreads();

        #pragma unroll
        for (int k16 = 0; k16 < 4; k16++) {
            unsigned a[2][4], b[4][4];
            #pragma unroll
            for (int mi = 0; mi < 2; mi++)
                ldsm4(a[mi][0], a[mi][1], a[mi][2], a[mi][3],
                      xs_b + buf * TB + aoff[mi] + k16 * 32);
            #pragma unroll
            for (int njp = 0; njp < 4; njp++)
                ldsm4(b[njp][0], b[njp][1], b[njp][2], b[njp][3],
                      ws_b + buf * TB + boff[njp] + k16 * 32);
            #pragma unroll
            for (int mi = 0; mi < 2; mi++)
                #pragma unroll
                for (int nj = 0; nj < 8; nj++)
                    mma16h(acc[mi][nj], a[mi], &b[nj >> 1][2 * (nj & 1)]);
        }
        __syncthreads();
    }

    #pragma unroll
    for (int mi = 0; mi < 2; mi++) {
        int row = m0 + wm * 32 + mi * 16 + g;
        int bb = row >> 11, s = row & (S_SZ - 1);
        #pragma unroll
        for (int nj = 0; nj < 8; nj++) {
            int col = n0 + wn * 64 + nj * 8 + 2 * t;
            int h = col >> 6, d = col & 63;
            float bs = (sel == 0) ? KLOG : 1.0f;
            float b0 = bias[col] * bs, b1 = bias[col + 1] * bs;
            float v0 = acc[mi][nj][0] + b0, v1 = acc[mi][nj][1] + b1;
            float v2 = acc[mi][nj][2] + b0, v3 = acc[mi][nj][3] + b1;
            size_t base0 = ((size_t)(bb * H_SZ + h) * S_SZ + s) * HD_SZ;
            size_t base1 = ((size_t)(bb * H_SZ + h) * S_SZ + s + 8) * HD_SZ;
            if (sel == 2) {
                *(float2*)(g_V + base0 + d) = make_float2(v0, v1);
                *(float2*)(g_V + base1 + d) = make_float2(v2, v3);
            } else {
                __half* hp = (sel == 0) ? g_Qh : g_Kh;
                *(__half2*)(hp + base0 + d) = __floats2half2_rn(v0, v1);
                *(__half2*)(hp + base1 + d) = __floats2half2_rn(v2, v3);
            }
        }
    }
}

__global__ __launch_bounds__(256, 2) void projqk(const float* __restrict__ bq,
                                                 const float* __restrict__ bk) {
    proj_body(blockIdx.z, blockIdx.x * 128, blockIdx.y * 128, blockIdx.z ? bk : bq);
}

// ---------------------------------------------------------------------------
// lse body: resident A = Q' (128 q-rows), streamed B = K. f16x2 exp epilogue.
// ---------------------------------------------------------------------------
__device__ __forceinline__ void lse_body(int bh, int q0) {
    extern __shared__ char smc[];
    const int TB = 128 * KSTR * 2;
    __half* Qs = (__half*)smc;
    __half* Ks = (__half*)(smc + TB);
    float (*red)[128] = (float(*)[128])(smc + 3 * TB);

    const int tid = threadIdx.x, lane = tid & 31, wid = tid >> 5;
    const int wm = wid >> 1, wn = wid & 1;
    const int g = lane >> 2, t = lane & 3;
    const __half* Qp = g_Qh + (size_t)bh * S_SZ * HD_SZ;
    const __half* Kp = g_Kh + (size_t)bh * S_SZ * HD_SZ;

    uint32_t qs_b = (uint32_t)__cvta_generic_to_shared(Qs);
    uint32_t ks_b = (uint32_t)__cvta_generic_to_shared(Ks);

    const int la = lane & 15, ha = lane >> 4;
    const int lbr = (lane & 7) + 8 * (lane >> 4);
    const int lbc = ((lane >> 3) & 1) * 8;
    uint32_t aoff[2], boff[4];
    #pragma unroll
    for (int mi = 0; mi < 2; mi++)
        aoff[mi] = qs_b + ((wm * 32 + mi * 16 + la) * KSTR + 8 * ha) * 2;
    #pragma unroll
    for (int njp = 0; njp < 4; njp++)
        boff[njp] = ((wn * 64 + njp * 16 + lbr) * KSTR + lbc) * 2;

    #pragma unroll
    for (int i = tid; i < 1024; i += 256) {
        int r = i >> 3, c8 = (i & 7) << 3;
        cpa16(qs_b + (r * KSTR + c8) * 2, Qp + (size_t)(q0 + r) * HD_SZ + c8);
    }
    cp_commit();

    auto issue = [&](int ktile, int buf) {
        int n0 = ktile * 128;
        #pragma unroll
        for (int i = tid; i < 1024; i += 256) {
            int r = i >> 3, c8 = (i & 7) << 3;
            cpa16(ks_b + buf * TB + (r * KSTR + c8) * 2, Kp + (size_t)(n0 + r) * HD_SZ + c8);
        }
        cp_commit();
    };

    issue(0, 0);
    cp_wait<0>();
    __syncthreads();

    float rs[2][2] = {};

    for (int i = 0; i < 16; i++) {
        int buf = i & 1;
        if (i + 1 < 16) { issue(i + 1, 1 - buf); cp_wait<1>(); }
        else cp_wait<0>();
        __syncthreads();

        float acc[2][8][4] = {};
        #pragma unroll
        for (int k16 = 0; k16 < 4; k16++) {
            unsigned a[2][4], b[4][4];
            #pragma unroll
            for (int mi = 0; mi < 2; mi++)
                ldsm4(a[mi][0], a[mi][1], a[mi][2], a[mi][3], aoff[mi] + k16 * 32);
            #pragma unroll
            for (int njp = 0; njp < 4; njp++)
                ldsm4(b[njp][0], b[njp][1], b[njp][2], b[njp][3],
                      ks_b + buf * TB + boff[njp] + k16 * 32);
            #pragma unroll
            for (int mi = 0; mi < 2; mi++)
                #pragma unroll
                for (int nj = 0; nj < 8; nj++)
                    mma16h(acc[mi][nj], a[mi], &b[nj >> 1][2 * (nj & 1)]);
        }

        #pragma unroll
        for (int mi = 0; mi < 2; mi++) {
            __half2 hg = __floats2half2_rn(0.f, 0.f), hg8 = hg;
            #pragma unroll
            for (int nj = 0; nj < 8; nj++) {
                hg  = __hadd2(hg,  h2ex2(__floats2half2_rn(acc[mi][nj][0], acc[mi][nj][1])));
                hg8 = __hadd2(hg8, h2ex2(__floats2half2_rn(acc[mi][nj][2], acc[mi][nj][3])));
            }
            float2 f0 = __half22float2(hg), f1 = __half22float2(hg8);
            rs[mi][0] += f0.x + f0.y;
            rs[mi][1] += f1.x + f1.y;
        }
        __syncthreads();
    }

    #pragma unroll
    for (int mi = 0; mi < 2; mi++)
        #pragma unroll
        for (int h2 = 0; h2 < 2; h2++) {
            float v = rs[mi][h2];
            v += __shfl_xor_sync(0xffffffffu, v, 1);
            v += __shfl_xor_sync(0xffffffffu, v, 2);
            if (t == 0) red[wn][wm * 32 + mi * 16 + g + 8 * h2] = v;
        }
    __syncthreads();
    if (tid < 128)
        g_Ri[bh * S_SZ + q0 + tid] = 1.0f / (red[0][tid] + red[1][tid]);
}

// Fused launch: blocks [0,256) do the V projection, [256,768) do lse.
__global__ __launch_bounds__(256, 2) void vproj_lse(const float* __restrict__ bv) {
    if (blockIdx.x < 256) {
        proj_body(2, (blockIdx.x & 7) * 128, (blockIdx.x >> 3) * 128, bv);
    } else {
        int idx = blockIdx.x - 256;
        lse_body(idx >> 4, (idx & 15) * 128);
    }
}

// ---------------------------------------------------------------------------
// Pass B (wk): resident A = K (128 keys), streamed B = Q' + Ri. f16x2 exp.
// ---------------------------------------------------------------------------
#define WK_SMEM (3 * 128 * KSTR * 2 + 2 * 128 * 4 + 2 * 128 * 4)
__global__ __launch_bounds__(256, 2) void wk_mma() {
    extern __shared__ char smc[];
    const int TB = 128 * KSTR * 2;
    __half* Kr = (__half*)smc;
    __half* Qs = (__half*)(smc + TB);
    float (*rsm)[128] = (float(*)[128])(smc + 3 * TB);
    float (*red)[128] = (float(*)[128])(smc + 3 * TB + 2 * 128 * 4);

    const int tid = threadIdx.x, lane = tid & 31, wid = tid >> 5;
    const int wm = wid >> 1, wn = wid & 1;
    const int g = lane >> 2, t = lane & 3;
    const int bh = blockIdx.y, k0 = blockIdx.x * 128;
    const __half* Qp = g_Qh + (size_t)bh * S_SZ * HD_SZ;
    const __half* Kp = g_Kh + (size_t)bh * S_SZ * HD_SZ;
    const float* Rp = g_Ri + bh * S_SZ;

    uint32_t kr_b = (uint32_t)__cvta_generic_to_shared(Kr);
    uint32_t qs_b = (uint32_t)__cvta_generic_to_shared(Qs);
    uint32_t rs_b = (uint32_t)__cvta_generic_to_shared(&rsm[0][0]);

    const int la = lane & 15, ha = lane >> 4;
    const int lbr = (lane & 7) + 8 * (lane >> 4);
    const int lbc = ((lane >> 3) & 1) * 8;
    uint32_t aoff[2], boff[4];
    #pragma unroll
    for (int mi = 0; mi < 2; mi++)
        aoff[mi] = kr_b + ((wm * 32 + mi * 16 + la) * KSTR + 8 * ha) * 2;
    #pragma unroll
    for (int njp = 0; njp < 4; njp++)
        boff[njp] = ((wn * 64 + njp * 16 + lbr) * KSTR + lbc) * 2;

    #pragma unroll
    for (int i = tid; i < 1024; i += 256) {
        int r = i >> 3, c8 = (i & 7) << 3;
        cpa16(kr_b + (r * KSTR + c8) * 2, Kp + (size_t)(k0 + r) * HD_SZ + c8);
    }
    cp_commit();

    auto issue = [&](int qtile, int buf) {
        int n0 = qtile * 128;
        #pragma unroll
        for (int i = tid; i < 1024; i += 256) {
            int r = i >> 3, c8 = (i & 7) << 3;
            cpa16(qs_b + buf * TB + (r * KSTR + c8) * 2, Qp + (size_t)(n0 + r) * HD_SZ + c8);
        }
        if (tid < 32) cpa16(rs_b + (buf * 128 + tid * 4) * 4, Rp + n0 + tid * 4);
        cp_commit();
    };

    issue(0, 0);
    cp_wait<0>();
    __syncthreads();

    float rs[2][2] = {};

    for (int i = 0; i < 16; i++) {
        int buf = i & 1;
        if (i + 1 < 16) { issue(i + 1, 1 - buf); cp_wait<1>(); }
        else cp_wait<0>();
        __syncthreads();

        float acc[2][8][4] = {};
        #pragma unroll
        for (int k16 = 0; k16 < 4; k16++) {
            unsigned a[2][4], b[4][4];
            #pragma unroll
            for (int mi = 0; mi < 2; mi++)
                ldsm4(a[mi][0], a[mi][1], a[mi][2], a[mi][3], aoff[mi] + k16 * 32);
            #pragma unroll
            for (int njp = 0; njp < 4; njp++)
                ldsm4(b[njp][0], b[njp][1], b[njp][2], b[njp][3],
                      qs_b + buf * TB + boff[njp] + k16 * 32);
            #pragma unroll
            for (int mi = 0; mi < 2; mi++)
                #pragma unroll
                for (int nj = 0; nj < 8; nj++)
                    mma16h(acc[mi][nj], a[mi], &b[nj >> 1][2 * (nj & 1)]);
        }

        __half2 hacc[2][2];
        hacc[0][0] = hacc[0][1] = hacc[1][0] = hacc[1][1] = __floats2half2_rn(0.f, 0.f);
        #pragma unroll
        for (int nj = 0; nj < 8; nj++) {
            int cb = wn * 64 + nj * 8 + 2 * t;
            __half2 rr = __floats2half2_rn(rsm[buf][cb], rsm[buf][cb + 1]);
            #pragma unroll
            for (int mi = 0; mi < 2; mi++) {
                hacc[mi][0] = __hfma2(h2ex2(__floats2half2_rn(acc[mi][nj][0], acc[mi][nj][1])), rr, hacc[mi][0]);
                hacc[mi][1] = __hfma2(h2ex2(__floats2half2_rn(acc[mi][nj][2], acc[mi][nj][3])), rr, hacc[mi][1]);
            }
        }
        #pragma unroll
        for (int mi = 0; mi < 2; mi++) {
            float2 f0 = __half22float2(hacc[mi][0]), f1 = __half22float2(hacc[mi][1]);
            rs[mi][0] += f0.x + f0.y;
            rs[mi][1] += f1.x + f1.y;
        }
        __syncthreads();
    }

    #pragma unroll
    for (int mi = 0; mi < 2; mi++)
        #pragma unroll
        for (int h2 = 0; h2 < 2; h2++) {
            float v = rs[mi][h2];
            v += __shfl_xor_sync(0xffffffffu, v, 1);
            v += __shfl_xor_sync(0xffffffffu, v, 2);
            if (t == 0) red[wn][wm * 32 + mi * 16 + g + 8 * h2] = v;
        }
    __syncthreads();
    if (tid < 128)
        g_w[bh * S_SZ + k0 + tid] = (red[0][tid] + red[1][tid]) * (1.0f / S_SZ);
}

// ---------------------------------------------------------------------------
// Output: out[b, h*64+d] = sum_k w[bh,k] * V[bh,k,d]. One block per bh.
// ---------------------------------------------------------------------------
__global__ __launch_bounds__(256) void outk(float* __restrict__ out) {
    __shared__ float red2[4][64];
    const int bh = blockIdx.x, tid = threadIdx.x;
    const int d = tid & 63, sl = tid >> 6;
    const float* Vp = g_V + (size_t)bh * S_SZ * HD_SZ;
    const float* wp = g_w + bh * S_SZ;
    float a = 0.f;
    #pragma unroll 4
    for (int k = sl * 512; k < (sl + 1) * 512; ++k)
        a = fmaf(wp[k], Vp[(size_t)k * HD_SZ + d], a);
    red2[sl][d] = a;
    __syncthreads();
    if (tid < 64) {
        float s = red2[0][tid] + red2[1][tid] + red2[2][tid] + red2[3][tid];
        int bb = bh >> 4, h = bh & 15;
        out[bb * D_SZ + h * HD_SZ + tid] = s;
    }
}

// ---------------------------------------------------------------------------
extern "C" void kernel_launch(void* const* d_in, const int* in_sizes, int n_in,
                              void* d_out, int out_size) {
    (void)in_sizes; (void)n_in; (void)out_size;
    const float* X  = (const float*)d_in[0];
    const float* Wq = (const float*)d_in[1];
    const float* bq = (const float*)d_in[2];
    const float* Wk = (const float*)d_in[3];
    const float* bk = (const float*)d_in[4];
    const float* Wv = (const float*)d_in[5];
    const float* bv = (const float*)d_in[6];
    float* out = (float*)d_out;

    cudaFuncSetAttribute(projqk,    cudaFuncAttributeMaxDynamicSharedMemorySize, PROJH_SMEM);
    cudaFuncSetAttribute(vproj_lse, cudaFuncAttributeMaxDynamicSharedMemorySize, PROJH_SMEM);
    cudaFuncSetAttribute(wk_mma,    cudaFuncAttributeMaxDynamicSharedMemorySize, WK_SMEM);

    prep_all<<<4096, 256>>>(X, Wq, Wk, Wv);

    dim3 gqk(D_SZ / 128, TOK_SZ / 128, 2);     // (8, 32, 2)
    projqk<<<gqk, 256, PROJH_SMEM>>>(bq, bk);

    vproj_lse<<<768, 256, PROJH_SMEM>>>(bv);   // 256 V-proj blocks + 512 lse blocks

    dim3 ga(S_SZ / 128, BH_SZ);                // (16, 32)
    wk_mma<<<ga, 256, WK_SMEM>>>();

    outk<<<BH_SZ, 256>>>(out);
}